// round 9
// baseline (speedup 1.0000x reference)
#include <cuda_runtime.h>

#define IMG_W 512
#define IMG_H 512
#define NBATCH 32
#define RSTRIP 16
#define BLOCK 256
// threads: 32 batches * (512/16 y-strips) * (512/4 x-strips) = 131072
#define TOTAL_THREADS (NBATCH * (IMG_H / RSTRIP) * (IMG_W / 4))
#define NBLOCKS (TOTAL_THREADS / BLOCK)   // 512
#define NPIX ((long long)NBATCH * IMG_H * IMG_W)

__device__ float2 g_partials[NBLOCKS];
__device__ unsigned int g_ticket = 0;     // reset by the last block each call

struct RowF { float dh[4]; float sh[4]; };

// Load one row of 4 pixels + halos. Halos come from neighbor lanes' float4
// via warp shuffle; only lane 0 / lane 31 touch memory for the halo (warp
// boundary), and image edges get 0. Caller guarantees y is warp-uniform.
__device__ __forceinline__ void load_row_w(const float* __restrict__ img, int y,
                                           int x0, int lane, float v[6]) {
    if ((unsigned)y < IMG_H) {
        const float* row = img + (size_t)y * IMG_W;
        float4 m = __ldg(reinterpret_cast<const float4*>(row + x0));
        v[1] = m.x; v[2] = m.y; v[3] = m.z; v[4] = m.w;
        float left  = __shfl_up_sync(0xffffffffu, m.w, 1);
        float right = __shfl_down_sync(0xffffffffu, m.x, 1);
        if (lane == 0)  left  = (x0 > 0)         ? __ldg(row + x0 - 1) : 0.f;
        if (lane == 31) right = (x0 + 4 < IMG_W) ? __ldg(row + x0 + 4) : 0.f;
        v[0] = left; v[5] = right;
    } else {
#pragma unroll
        for (int k = 0; k < 6; ++k) v[k] = 0.f;
    }
}

__device__ __forceinline__ void make_row(const float v[6], RowF& r) {
#pragma unroll
    for (int j = 0; j < 4; ++j) {
        r.dh[j] = v[j + 2] - v[j];                       // horizontal [-1,0,1]
        r.sh[j] = v[j] + 2.f * v[j + 1] + v[j + 2];      // horizontal [1,2,1]
    }
}

__global__ __launch_bounds__(BLOCK, 2)   // pin regs <= 128 -> 2 blocks/SM
void fuse_main(const float* __restrict__ A, const float* __restrict__ Bi,
               const float* __restrict__ F, const int* __restrict__ scheme,
               float* __restrict__ out) {
    int t   = blockIdx.x * BLOCK + threadIdx.x;
    int b   = t >> 12;          // / 4096 strips per image
    int rem = t & 4095;
    int ys  = rem >> 7;         // 32 y-strips
    int xs  = rem & 127;        // 128 x-strips
    int x0  = xs << 2;
    int y0  = ys * RSTRIP;
    int lane = threadIdx.x & 31;

    size_t off = (size_t)b * IMG_H * IMG_W;
    const float* pA = A  + off;
    const float* pB = Bi + off;
    const float* pF = F  + off;
    // JAX default x64-disabled: fuse_scheme materializes as int32
    const bool avg = (scheme[b] == 0);

    RowF rA[3], rB[3], rF[3];
    float sumL = 0.f, sumG = 0.f;

    // Software pipeline: v* = current row, n* = prefetched next row.
    float vA[6], vB[6], vF[6];
    load_row_w(pA, y0 - 1, x0, lane, vA);
    load_row_w(pB, y0 - 1, x0, lane, vB);
    load_row_w(pF, y0 - 1, x0, lane, vF);

#pragma unroll
    for (int i = 0; i < RSTRIP + 2; ++i) {
        float nA[6], nB[6], nF[6];
        if (i < RSTRIP + 1) {               // prefetch row i+1 before computing row i
            load_row_w(pA, y0 + i, x0, lane, nA);
            load_row_w(pB, y0 + i, x0, lane, nB);
            load_row_w(pF, y0 + i, x0, lane, nF);
        }

        int cur = i % 3;
        make_row(vA, rA[cur]);
        make_row(vB, rB[cur]);
        make_row(vF, rF[cur]);

        // l_loss contribution: rows y0 .. y0+R-1  (i in [1, R])
        if (i >= 1 && i <= RSTRIP) {
#pragma unroll
            for (int j = 0; j < 4; ++j) {
                float ab = avg ? 0.5f * (vA[j + 1] + vB[j + 1])
                               : fmaxf(vA[j + 1], vB[j + 1]);
                sumL += fabsf(ab - vF[j + 1]);
            }
        }

        // grad_loss for output row y-1 once rows y-2, y-1, y are resident
        if (i >= 2) {
            int r0 = (i - 2) % 3, r1 = (i - 1) % 3;
#pragma unroll
            for (int j = 0; j < 4; ++j) {
                float gxA = rA[r0].dh[j] + 2.f * rA[r1].dh[j] + rA[cur].dh[j];
                float gyA = rA[r0].sh[j] - rA[cur].sh[j];
                float sA  = fabsf(gxA) + fabsf(gyA);
                float gxB = rB[r0].dh[j] + 2.f * rB[r1].dh[j] + rB[cur].dh[j];
                float gyB = rB[r0].sh[j] - rB[cur].sh[j];
                float sB  = fabsf(gxB) + fabsf(gyB);
                float gxF = rF[r0].dh[j] + 2.f * rF[r1].dh[j] + rF[cur].dh[j];
                float gyF = rF[r0].sh[j] - rF[cur].sh[j];
                float sF  = fabsf(gxF) + fabsf(gyF);
                sumG += fabsf(sF - fmaxf(sA, sB));
            }
        }

        // shift pipeline (renamed away by the unroll)
#pragma unroll
        for (int k = 0; k < 6; ++k) { vA[k] = nA[k]; vB[k] = nB[k]; vF[k] = nF[k]; }
    }

    // ---- Block reduction (deterministic, no float atomics) ----
#pragma unroll
    for (int o = 16; o > 0; o >>= 1) {
        sumL += __shfl_down_sync(0xffffffffu, sumL, o);
        sumG += __shfl_down_sync(0xffffffffu, sumG, o);
    }
    __shared__ float sL[BLOCK / 32], sG[BLOCK / 32];
    __shared__ bool s_last;
    int wid = threadIdx.x >> 5;
    if (lane == 0) { sL[wid] = sumL; sG[wid] = sumG; }
    __syncthreads();
    if (threadIdx.x == 0) {
        float l = 0.f, g = 0.f;
#pragma unroll
        for (int k = 0; k < BLOCK / 32; ++k) { l += sL[k]; g += sG[k]; }
        g_partials[blockIdx.x] = make_float2(l, g);
        __threadfence();
        unsigned int ticket = atomicAdd(&g_ticket, 1u);
        s_last = (ticket == NBLOCKS - 1);
    }
    __syncthreads();

    // ---- Last block finalizes: fixed-order sum over all partials ----
    if (s_last) {
        float l = 0.f, g = 0.f;
#pragma unroll
        for (int k = 0; k < NBLOCKS / BLOCK; ++k) {
            float2 p = g_partials[threadIdx.x + k * BLOCK];
            l += p.x; g += p.y;
        }
#pragma unroll
        for (int o = 16; o > 0; o >>= 1) {
            l += __shfl_down_sync(0xffffffffu, l, o);
            g += __shfl_down_sync(0xffffffffu, g, o);
        }
        if (lane == 0) { sL[wid] = l; sG[wid] = g; }
        __syncthreads();
        if (threadIdx.x == 0) {
            float L = 0.f, G = 0.f;
#pragma unroll
            for (int k = 0; k < BLOCK / 32; ++k) { L += sL[k]; G += sG[k]; }
            out[0] = (L + G) * (1.0f / (float)NPIX);  // l_loss + grad_loss; 0.0*cs_loss dropped
            g_ticket = 0;   // reset for next graph replay
        }
    }
}

extern "C" void kernel_launch(void* const* d_in, const int* in_sizes, int n_in,
                              void* d_out, int out_size) {
    (void)in_sizes; (void)n_in; (void)out_size;
    const float* A      = (const float*)d_in[0];
    const float* B      = (const float*)d_in[1];
    const float* F      = (const float*)d_in[2];
    const int*   scheme = (const int*)d_in[3];
    float* out = (float*)d_out;

    fuse_main<<<NBLOCKS, BLOCK>>>(A, B, F, scheme, out);
}

// round 11
// speedup vs baseline: 2.3463x; 2.3463x over previous
#include <cuda_runtime.h>

#define IMG_W 512
#define IMG_H 512
#define NBATCH 32
#define RSTRIP 16
#define BLOCK 256
// threads: 32 batches * (512/16 y-strips) * (512/4 x-strips) = 131072
#define TOTAL_THREADS (NBATCH * (IMG_H / RSTRIP) * (IMG_W / 4))
#define NBLOCKS (TOTAL_THREADS / BLOCK)   // 512
#define NPIX ((long long)NBATCH * IMG_H * IMG_W)

__device__ float2 g_partials[NBLOCKS];
__device__ unsigned int g_ticket = 0;     // reset by the last block each call

struct RowF { float dh[4]; float sh[4]; };

// Main-body float4 load (the DRAM-bound part). No consumer until next iter.
__device__ __forceinline__ float4 load4(const float* __restrict__ img, int y, int x0) {
    if ((unsigned)y < IMG_H)
        return __ldg(reinterpret_cast<const float4*>(img + (size_t)y * IMG_W + x0));
    return make_float4(0.f, 0.f, 0.f, 0.f);
}

// Assemble 6-wide row from the (already prefetched) float4 + 2 halo scalars.
// Halo scalars hit lines the warp already pulled -> L1/L2 hits, cheap.
__device__ __forceinline__ void assemble(const float* __restrict__ img, int y, int x0,
                                         float4 m, float v[6]) {
    v[1] = m.x; v[2] = m.y; v[3] = m.z; v[4] = m.w;
    if ((unsigned)y < IMG_H) {
        const float* row = img + (size_t)y * IMG_W;
        v[0] = (x0 > 0)         ? __ldg(row + x0 - 1) : 0.f;
        v[5] = (x0 + 4 < IMG_W) ? __ldg(row + x0 + 4) : 0.f;
    } else {
        v[0] = 0.f; v[5] = 0.f;
    }
}

__device__ __forceinline__ void make_row(const float v[6], RowF& r) {
#pragma unroll
    for (int j = 0; j < 4; ++j) {
        r.dh[j] = v[j + 2] - v[j];                       // horizontal [-1,0,1]
        r.sh[j] = v[j] + 2.f * v[j + 1] + v[j + 2];      // horizontal [1,2,1]
    }
}

__global__ __launch_bounds__(BLOCK, 2)   // keep 2 blocks/SM residency
void fuse_main(const float* __restrict__ A, const float* __restrict__ Bi,
               const float* __restrict__ F, const int* __restrict__ scheme,
               float* __restrict__ out) {
    int t   = blockIdx.x * BLOCK + threadIdx.x;
    int b   = t >> 12;          // / 4096 strips per image
    int rem = t & 4095;
    int ys  = rem >> 7;         // 32 y-strips
    int xs  = rem & 127;        // 128 x-strips
    int x0  = xs << 2;
    int y0  = ys * RSTRIP;

    size_t off = (size_t)b * IMG_H * IMG_W;
    const float* pA = A  + off;
    const float* pB = Bi + off;
    const float* pF = F  + off;
    // JAX default x64-disabled: fuse_scheme materializes as int32
    const bool avg = (scheme[b] == 0);

    RowF rA[3], rB[3], rF[3];
    float sumL = 0.f, sumG = 0.f;

    // Prefetch registers: float4 for the row about to be computed.
    float4 cA = load4(pA, y0 - 1, x0);
    float4 cB = load4(pB, y0 - 1, x0);
    float4 cF = load4(pF, y0 - 1, x0);

#pragma unroll
    for (int i = 0; i < RSTRIP + 2; ++i) {
        int y = y0 - 1 + i;

        // 1) Issue next row's float4 loads FIRST (stay outstanding all iter).
        float4 nA, nB, nF;
        if (i < RSTRIP + 1) {
            nA = load4(pA, y + 1, x0);
            nB = load4(pB, y + 1, x0);
            nF = load4(pF, y + 1, x0);
        }

        // 2) Assemble current row (halo scalars = cache hits).
        float vA[6], vB[6], vF[6];
        assemble(pA, y, x0, cA, vA);
        assemble(pB, y, x0, cB, vB);
        assemble(pF, y, x0, cF, vF);

        int cur = i % 3;
        make_row(vA, rA[cur]);
        make_row(vB, rB[cur]);
        make_row(vF, rF[cur]);

        // l_loss contribution: rows y0 .. y0+R-1  (i in [1, R])
        if (i >= 1 && i <= RSTRIP) {
#pragma unroll
            for (int j = 0; j < 4; ++j) {
                float ab = avg ? 0.5f * (vA[j + 1] + vB[j + 1])
                               : fmaxf(vA[j + 1], vB[j + 1]);
                sumL += fabsf(ab - vF[j + 1]);
            }
        }

        // grad_loss for output row y-1 once rows y-2, y-1, y are resident
        if (i >= 2) {
            int r0 = (i - 2) % 3, r1 = (i - 1) % 3;
#pragma unroll
            for (int j = 0; j < 4; ++j) {
                float gxA = rA[r0].dh[j] + 2.f * rA[r1].dh[j] + rA[cur].dh[j];
                float gyA = rA[r0].sh[j] - rA[cur].sh[j];
                float sA  = fabsf(gxA) + fabsf(gyA);
                float gxB = rB[r0].dh[j] + 2.f * rB[r1].dh[j] + rB[cur].dh[j];
                float gyB = rB[r0].sh[j] - rB[cur].sh[j];
                float sB  = fabsf(gxB) + fabsf(gyB);
                float gxF = rF[r0].dh[j] + 2.f * rF[r1].dh[j] + rF[cur].dh[j];
                float gyF = rF[r0].sh[j] - rF[cur].sh[j];
                float sF  = fabsf(gxF) + fabsf(gyF);
                sumG += fabsf(sF - fmaxf(sA, sB));
            }
        }

        // 3) Rotate prefetch registers.
        cA = nA; cB = nB; cF = nF;
    }

    // ---- Block reduction (deterministic, no float atomics) ----
#pragma unroll
    for (int o = 16; o > 0; o >>= 1) {
        sumL += __shfl_down_sync(0xffffffffu, sumL, o);
        sumG += __shfl_down_sync(0xffffffffu, sumG, o);
    }
    __shared__ float sL[BLOCK / 32], sG[BLOCK / 32];
    __shared__ bool s_last;
    int lane = threadIdx.x & 31, wid = threadIdx.x >> 5;
    if (lane == 0) { sL[wid] = sumL; sG[wid] = sumG; }
    __syncthreads();
    if (threadIdx.x == 0) {
        float l = 0.f, g = 0.f;
#pragma unroll
        for (int k = 0; k < BLOCK / 32; ++k) { l += sL[k]; g += sG[k]; }
        g_partials[blockIdx.x] = make_float2(l, g);
        __threadfence();
        unsigned int ticket = atomicAdd(&g_ticket, 1u);
        s_last = (ticket == NBLOCKS - 1);
    }
    __syncthreads();

    // ---- Last block finalizes: fixed-order sum over all partials ----
    if (s_last) {
        float l = 0.f, g = 0.f;
#pragma unroll
        for (int k = 0; k < NBLOCKS / BLOCK; ++k) {
            float2 p = g_partials[threadIdx.x + k * BLOCK];
            l += p.x; g += p.y;
        }
#pragma unroll
        for (int o = 16; o > 0; o >>= 1) {
            l += __shfl_down_sync(0xffffffffu, l, o);
            g += __shfl_down_sync(0xffffffffu, g, o);
        }
        if (lane == 0) { sL[wid] = l; sG[wid] = g; }
        __syncthreads();
        if (threadIdx.x == 0) {
            float L = 0.f, G = 0.f;
#pragma unroll
            for (int k = 0; k < BLOCK / 32; ++k) { L += sL[k]; G += sG[k]; }
            out[0] = (L + G) * (1.0f / (float)NPIX);  // l_loss + grad_loss; 0.0*cs_loss dropped
            g_ticket = 0;   // reset for next graph replay
        }
    }
}

extern "C" void kernel_launch(void* const* d_in, const int* in_sizes, int n_in,
                              void* d_out, int out_size) {
    (void)in_sizes; (void)n_in; (void)out_size;
    const float* A      = (const float*)d_in[0];
    const float* B      = (const float*)d_in[1];
    const float* F      = (const float*)d_in[2];
    const int*   scheme = (const int*)d_in[3];
    float* out = (float*)d_out;

    fuse_main<<<NBLOCKS, BLOCK>>>(A, B, F, scheme, out);
}